// round 12
// baseline (speedup 1.0000x reference)
#include <cuda_runtime.h>

// LatentLinearModel: r[i] = dot(U[users[i]], V[jokes[i]]) + a[users[i]] + b[jokes[i]] + g
// B = 1048576, K = 64.
//
// Round 12: mechanism probe - fetch gather rows via cp.async.bulk (UBLKCP /
// TMA-bulk engine) instead of per-thread cp.async through L1tex. The ~248-line
// per-SM L1tex queue is the best explanation for the 61%-of-HBM plateau that
// R1-R11 mapped out; the bulk path tracks in-flight bytes via mbarrier
// transactions instead of per-thread queue entries, and issues ONE instruction
// per 256B row (128/block vs 2048 LDGSTS).
// Tile shape, smem budget and compute phase are identical to the proven R4.

#define TPR    16                   // threads per row (compute phase)
#define RPG    4                    // rows per 16-lane group (compute phase)
#define BLOCK  256
#define RPB    64                   // rows per block
#define ROW_BYTES 256               // K=64 floats

__global__ void __launch_bounds__(BLOCK)
latent_linear_kernel(const int* __restrict__ users,
                     const int* __restrict__ jokes,
                     const float* __restrict__ U,
                     const float* __restrict__ V,
                     const float* __restrict__ a,
                     const float* __restrict__ b,
                     const float* __restrict__ g,
                     float* __restrict__ out,
                     int B) {
    __shared__ alignas(128) float4 sU[RPB][TPR];   // 16 KB
    __shared__ alignas(128) float4 sV[RPB][TPR];   // 16 KB
    __shared__ alignas(8) unsigned long long mbar;

    const int tid  = threadIdx.x;
    const int row0 = blockIdx.x * RPB;
    if (row0 >= B) return;
    const int n_rows = (B - row0 < RPB) ? (B - row0) : RPB;

    unsigned mbar_s = (unsigned)__cvta_generic_to_shared(&mbar);

    // ---- init mbarrier (1 arrival, carried by the expect_tx below) ----
    if (tid == 0) {
        asm volatile("mbarrier.init.shared.b64 [%0], 1;" :: "r"(mbar_s) : "memory");
    }
    __syncthreads();

    // ---- issue phase: one 256B bulk copy per row, threads 0..127 ----
    if (tid == 0) {
        asm volatile("mbarrier.arrive.expect_tx.shared.b64 _, [%0], %1;"
                     :: "r"(mbar_s), "r"((unsigned)(2 * n_rows * ROW_BYTES)) : "memory");
    }
    if (tid < n_rows) {
        int u = __ldg(&users[row0 + tid]);
        unsigned dst = (unsigned)__cvta_generic_to_shared(&sU[tid][0]);
        const void* src = (const char*)U + (size_t)u * ROW_BYTES;
        asm volatile(
            "cp.async.bulk.shared::cluster.global.mbarrier::complete_tx::bytes "
            "[%0], [%1], %2, [%3];"
            :: "r"(dst), "l"(src), "r"(ROW_BYTES), "r"(mbar_s) : "memory");
    } else if (tid < 2 * n_rows && tid >= RPB) {
        int r = tid - RPB;
        int j = __ldg(&jokes[row0 + r]);
        unsigned dst = (unsigned)__cvta_generic_to_shared(&sV[r][0]);
        const void* src = (const char*)V + (size_t)j * ROW_BYTES;
        asm volatile(
            "cp.async.bulk.shared::cluster.global.mbarrier::complete_tx::bytes "
            "[%0], [%1], %2, [%3];"
            :: "r"(dst), "l"(src), "r"(ROW_BYTES), "r"(mbar_s) : "memory");
    }

    // ---- overlap: bias + index loads for the compute mapping ----
    const int lane  = tid & (TPR - 1);
    const int lrow0 = (tid >> 4) * RPG;
    int us[RPG], js[RPG];
    {
        int rb = row0 + lrow0;
        int4 ui = __ldg((const int4*)(users + rb));
        int4 ji = __ldg((const int4*)(jokes + rb));
        us[0] = ui.x; us[1] = ui.y; us[2] = ui.z; us[3] = ui.w;
        js[0] = ji.x; js[1] = ji.y; js[2] = ji.z; js[3] = ji.w;
    }
    float bias[RPG];
    if (lane == 0) {
#pragma unroll
        for (int r = 0; r < RPG; r++)
            bias[r] = __ldg(&a[us[r]]) + __ldg(&b[js[r]]);
    }
    float gg = __ldg(&g[0]);

    // ---- wait for all 32KB of bulk copies (parity 0, acquire) ----
    {
        unsigned done;
        asm volatile(
            "{\n\t"
            ".reg .pred p;\n\t"
            "mbarrier.try_wait.parity.acquire.cta.shared::cta.b64 p, [%1], 0;\n\t"
            "selp.b32 %0, 1, 0, p;\n\t"
            "}"
            : "=r"(done) : "r"(mbar_s) : "memory");
        if (!done) {
            asm volatile(
                "{\n\t"
                ".reg .pred P1;\n\t"
                "WL_%=:\n\t"
                "mbarrier.try_wait.parity.acquire.cta.shared::cta.b64 P1, [%0], 0, 0x989680;\n\t"
                "@P1 bra.uni WD_%=;\n\t"
                "bra.uni WL_%=;\n\t"
                "WD_%=:\n\t"
                "}"
                :: "r"(mbar_s) : "memory");
        }
    }

    // ---- compute: dot + 16-lane reduction per row (same as R4) ----
#pragma unroll
    for (int r = 0; r < RPG; r++) {
        if (lrow0 + r >= n_rows) break;
        float4 uu = sU[lrow0 + r][lane];
        float4 vv = sV[lrow0 + r][lane];
        float d = uu.x * vv.x + uu.y * vv.y + uu.z * vv.z + uu.w * vv.w;
        d += __shfl_xor_sync(0xffffffffu, d, 8);
        d += __shfl_xor_sync(0xffffffffu, d, 4);
        d += __shfl_xor_sync(0xffffffffu, d, 2);
        d += __shfl_xor_sync(0xffffffffu, d, 1);
        if (lane == 0) {
            out[row0 + lrow0 + r] = d + bias[r] + gg;
        }
    }
}

extern "C" void kernel_launch(void* const* d_in, const int* in_sizes, int n_in,
                              void* d_out, int out_size) {
    // metadata order: users, jokes, U, V, a, b, g
    const int*   users = (const int*)d_in[0];
    const int*   jokes = (const int*)d_in[1];
    const float* U     = (const float*)d_in[2];
    const float* V     = (const float*)d_in[3];
    const float* a     = (const float*)d_in[4];
    const float* b     = (const float*)d_in[5];
    const float* g     = (const float*)d_in[6];
    float* out = (float*)d_out;

    int B = in_sizes[0];

    int grid = (B + RPB - 1) / RPB;
    latent_linear_kernel<<<grid, BLOCK>>>(users, jokes, U, V, a, b, g, out, B);
}

// round 13
// speedup vs baseline: 1.1838x; 1.1838x over previous
#include <cuda_runtime.h>

// LatentLinearModel: r[i] = dot(U[users[i]], V[jokes[i]]) + a[users[i]] + b[jokes[i]] + g
// B = 1048576, K = 64.
//
// Round 13: R4 with its one remaining inefficiency removed, and NOTHING else
// changed. R4 = issue 32KB -> wait_group 0 -> compute (zero bytes in flight
// during compute). Here the same 64-row tile is split into two 32-row commit
// groups: wait_group 1 lets S0's compute overlap S1's in-flight window.
// One-shot blocks (no persistence), same 32KB smem, same 5 blocks/SM, same
// register __ldg biases, same compute phase. R6 tried this idea but bundled
// persistence + cp.async4 biases + lambda overhead, which each hurt; this is
// the deconfounded version.

#define TPR    16                   // threads per row
#define RPG    2                    // rows per 16-lane group PER STAGE
#define BLOCK  256
#define GROUPS (BLOCK / TPR)        // 16
#define SROWS  (GROUPS * RPG)       // 32 rows per stage
#define RPB    (2 * SROWS)          // 64 rows per block

__device__ __forceinline__ void cp_async16(void* smem, const void* gmem) {
    unsigned s = (unsigned)__cvta_generic_to_shared(smem);
    asm volatile("cp.async.cg.shared.global [%0], [%1], 16;" :: "r"(s), "l"(gmem));
}

__global__ void __launch_bounds__(BLOCK)
latent_linear_kernel(const int* __restrict__ users,
                     const int* __restrict__ jokes,
                     const float4* __restrict__ U4,
                     const float4* __restrict__ V4,
                     const float* __restrict__ a,
                     const float* __restrict__ b,
                     const float* __restrict__ g,
                     float* __restrict__ out,
                     int B) {
    __shared__ float4 sU[2][SROWS][TPR];   // 2 x 8 KB
    __shared__ float4 sV[2][SROWS][TPR];   // 2 x 8 KB

    const int lane  = threadIdx.x & (TPR - 1);
    const int group = threadIdx.x >> 4;
    const int lr0   = group * RPG;                 // local row base within a stage
    const int base  = blockIdx.x * RPB;
    if (base >= B) return;

    // Global row bases for the two stages handled by this group.
    const int r0s0 = base + lr0;                   // stage 0 rows [r0s0, r0s0+1]
    const int r0s1 = base + SROWS + lr0;           // stage 1 rows

    // ---- Phase 1: index loads for BOTH stages (int2 per stage, 8B aligned) ----
    int2 u0 = __ldg((const int2*)(users + r0s0));
    int2 j0 = __ldg((const int2*)(jokes + r0s0));
    int2 u1 = __ldg((const int2*)(users + r0s1));
    int2 j1 = __ldg((const int2*)(jokes + r0s1));
    int us[4] = {u0.x, u0.y, u1.x, u1.y};
    int js[4] = {j0.x, j0.y, j1.x, j1.y};

    // ---- Phase 2a: issue stage 0 gathers, commit ----
#pragma unroll
    for (int r = 0; r < RPG; r++) {
        cp_async16(&sU[0][lr0 + r][lane], &U4[(size_t)us[r] * 16 + lane]);
        cp_async16(&sV[0][lr0 + r][lane], &V4[(size_t)js[r] * 16 + lane]);
    }
    asm volatile("cp.async.commit_group;");

    // ---- Phase 2b: issue stage 1 gathers, commit ----
#pragma unroll
    for (int r = 0; r < RPG; r++) {
        cp_async16(&sU[1][lr0 + r][lane], &U4[(size_t)us[2 + r] * 16 + lane]);
        cp_async16(&sV[1][lr0 + r][lane], &V4[(size_t)js[2 + r] * 16 + lane]);
    }
    asm volatile("cp.async.commit_group;");

    // Bias loads fly concurrently with the gathers (lane 0 only, registers).
    float bias[4];
    if (lane == 0) {
#pragma unroll
        for (int r = 0; r < 4; r++)
            bias[r] = __ldg(&a[us[r]]) + __ldg(&b[js[r]]);
    }
    float gg = __ldg(&g[0]);

    // ---- Phase 3a: stage 0 compute overlaps stage 1 in-flight ----
    asm volatile("cp.async.wait_group 1;" ::: "memory");
#pragma unroll
    for (int r = 0; r < RPG; r++) {
        float4 uu = sU[0][lr0 + r][lane];
        float4 vv = sV[0][lr0 + r][lane];
        float d = uu.x * vv.x + uu.y * vv.y + uu.z * vv.z + uu.w * vv.w;
        d += __shfl_xor_sync(0xffffffffu, d, 8);
        d += __shfl_xor_sync(0xffffffffu, d, 4);
        d += __shfl_xor_sync(0xffffffffu, d, 2);
        d += __shfl_xor_sync(0xffffffffu, d, 1);
        if (lane == 0) {
            out[r0s0 + r] = d + bias[r] + gg;
        }
    }

    // ---- Phase 3b: stage 1 compute ----
    asm volatile("cp.async.wait_group 0;" ::: "memory");
#pragma unroll
    for (int r = 0; r < RPG; r++) {
        float4 uu = sU[1][lr0 + r][lane];
        float4 vv = sV[1][lr0 + r][lane];
        float d = uu.x * vv.x + uu.y * vv.y + uu.z * vv.z + uu.w * vv.w;
        d += __shfl_xor_sync(0xffffffffu, d, 8);
        d += __shfl_xor_sync(0xffffffffu, d, 4);
        d += __shfl_xor_sync(0xffffffffu, d, 2);
        d += __shfl_xor_sync(0xffffffffu, d, 1);
        if (lane == 0) {
            out[r0s1 + r] = d + bias[2 + r] + gg;
        }
    }
}

extern "C" void kernel_launch(void* const* d_in, const int* in_sizes, int n_in,
                              void* d_out, int out_size) {
    // metadata order: users, jokes, U, V, a, b, g
    const int*    users = (const int*)d_in[0];
    const int*    jokes = (const int*)d_in[1];
    const float4* U4    = (const float4*)d_in[2];
    const float4* V4    = (const float4*)d_in[3];
    const float*  a     = (const float*)d_in[4];
    const float*  b     = (const float*)d_in[5];
    const float*  g     = (const float*)d_in[6];
    float* out = (float*)d_out;

    int B = in_sizes[0];

    int grid = (B + RPB - 1) / RPB;
    latent_linear_kernel<<<grid, BLOCK>>>(users, jokes, U4, V4, a, b, g, out, B);
}